// round 4
// baseline (speedup 1.0000x reference)
#include <cuda_runtime.h>
#include <math.h>

#define B 8
#define S 4096
#define D 1024
#define NEXP 16
#define P 4
#define H 2048
#define NP 64            // NEXP*P
#define TOK (B*S)        // 32768
#define ETOK (B*P)       // 32 tokens per expert
#define LN_EPS 1e-5f

// packed f32x2 fma (Blackwell): d = a*b + c on both halves
__device__ __forceinline__ float2 ffma2(float2 a, float2 b, float2 c) {
    unsigned long long ua = *reinterpret_cast<unsigned long long*>(&a);
    unsigned long long ub = *reinterpret_cast<unsigned long long*>(&b);
    unsigned long long uc = *reinterpret_cast<unsigned long long*>(&c);
    unsigned long long ud;
    asm("fma.rn.f32x2 %0, %1, %2, %3;" : "=l"(ud) : "l"(ua), "l"(ub), "l"(uc));
    return *reinterpret_cast<float2*>(&ud);
}
__device__ __forceinline__ float2 dup2(float v) { return make_float2(v, v); }

// ---------------- static device scratch -------------------------------------
__device__ float  g_ph[D*NP];          // normalized phi * scale, layout [d][np]
__device__ float  g_wnum[TOK*NP];      // exp(l-shift) * inv||x||
__device__ float  g_epart[TOK*P];      // sum_n exp(l-shift) per p
__device__ double g_Zd[B*NP];
__device__ float  g_Zf[B*NP];          // 1/Zd
__device__ double g_Zb[B];
__device__ double g_iZb[B];
__device__ double g_ptn[B*P];
__device__ float  g_shift;
__device__ float  g_xs[B*NP*D];
__device__ float  g_h[NEXP*ETOK*H];
__device__ float  g_r[NEXP*ETOK*D];
__device__ float  g_ys[B*NP*D];
__device__ double g_mi;

// ---------------- init -------------------------------------------------------
__global__ void k_init(const float* __restrict__ task_emb) {
    int idx = blockIdx.x * 256 + threadIdx.x;
    if (idx < B*NP*D) {
        int d  = idx % D;
        int np = (idx / D) % NP;
        g_xs[idx] = task_emb[(np & 3) * D + d];
    }
    if (blockIdx.x < 2) g_Zd[blockIdx.x * 256 + threadIdx.x] = 0.0;
    if (blockIdx.x == 2) {
        if (threadIdx.x < B*P) g_ptn[threadIdx.x] = 0.0;
        if (threadIdx.x == 0)  g_mi = 0.0;
    }
}

// ---------------- normalize phi ----------------------------------------------
__global__ void k_ph(const float* __restrict__ phi, const float* __restrict__ scale) {
    int np = blockIdx.x;
    __shared__ float red[256];
    int t = threadIdx.x;
    float ss = 0.f;
    for (int d = t; d < D; d += 256) { float v = phi[d*NP + np]; ss += v*v; }
    red[t] = ss; __syncthreads();
    for (int o = 128; o > 0; o >>= 1) { if (t < o) red[t] += red[t+o]; __syncthreads(); }
    float inv = scale[0] / fmaxf(sqrtf(red[0]), 1e-12f);
    for (int d = t; d < D; d += 256)
        g_ph[d*NP + np] = phi[d*NP + np] * inv;
    if (np == 0 && t == 0) g_shift = fabsf(scale[0]);
}

// ---------------- logits GEMM (f32x2) + fused softmax epilogues --------------
// tile: 64 tokens x 64 np; thread (tg 0..15: 4 tok, ng 0..15: np quad ng*4..+3)
__global__ void k_logits(const float* __restrict__ x, float* __restrict__ out_cmb) {
    __shared__ __align__(16) float2 x2[64*32];    // [tok][dd] dup  16KB
    __shared__ __align__(16) float2 ph2[32*32];   // [dd][pair]     8KB
    __shared__ float ssq_sm[64];
    __shared__ float zsm[64*16];                  // 4KB
    __shared__ float ptn_sm[4];
    int t = threadIdx.x;
    int tok0 = blockIdx.x * 64;
    int b = tok0 >> 12;
    int tg = t >> 4, ng = t & 15;
    int ltok = t >> 2, lq = t & 3;
    int ldd = t >> 3, lpr = (t & 7) * 4;
    if (t < 4) ptn_sm[t] = 0.f;
    float ssq = 0.f;
    float2 acc[4][2];
    #pragma unroll
    for (int i = 0; i < 4; i++) { acc[i][0] = dup2(0.f); acc[i][1] = dup2(0.f); }
    for (int d0 = 0; d0 < D; d0 += 32) {
        const float4* xr = (const float4*)(x + (size_t)(tok0+ltok)*D + d0 + lq*8);
        float4 v0 = xr[0], v1 = xr[1];
        ssq += v0.x*v0.x + v0.y*v0.y + v0.z*v0.z + v0.w*v0.w
             + v1.x*v1.x + v1.y*v1.y + v1.z*v1.z + v1.w*v1.w;
        int xb = ltok*32 + lq*8;
        x2[xb+0]=dup2(v0.x); x2[xb+1]=dup2(v0.y); x2[xb+2]=dup2(v0.z); x2[xb+3]=dup2(v0.w);
        x2[xb+4]=dup2(v1.x); x2[xb+5]=dup2(v1.y); x2[xb+6]=dup2(v1.z); x2[xb+7]=dup2(v1.w);
        const float4* pr = (const float4*)(g_ph + (size_t)(d0+ldd)*NP + lpr*2);
        *(float4*)&ph2[ldd*32 + lpr]     = pr[0];
        *(float4*)&ph2[ldd*32 + lpr + 2] = pr[1];
        __syncthreads();
        #pragma unroll 4
        for (int dd = 0; dd < 32; dd++) {
            float4 bb = *(const float4*)&ph2[dd*32 + ng*2];
            float2 b0 = make_float2(bb.x, bb.y), b1 = make_float2(bb.z, bb.w);
            #pragma unroll
            for (int i = 0; i < 4; i++) {
                float2 a = x2[(tg*4+i)*32 + dd];
                acc[i][0] = ffma2(a, b0, acc[i][0]);
                acc[i][1] = ffma2(a, b1, acc[i][1]);
            }
        }
        __syncthreads();
    }
    ssq += __shfl_xor_sync(~0u, ssq, 1);
    ssq += __shfl_xor_sync(~0u, ssq, 2);
    if (lq == 0) ssq_sm[ltok] = 1.f / fmaxf(sqrtf(ssq), 1e-12f);
    __syncthreads();
    float shift = g_shift;
    float znp[4] = {0,0,0,0};
    float ptnl[4] = {0,0,0,0};
    #pragma unroll
    for (int i = 0; i < 4; i++) {
        int tk = tg*4 + i;
        size_t tok = tok0 + tk;
        float inv = ssq_sm[tk];
        float e0 = expf(acc[i][0].x*inv - shift);
        float e1 = expf(acc[i][0].y*inv - shift);
        float e2 = expf(acc[i][1].x*inv - shift);
        float e3 = expf(acc[i][1].y*inv - shift);
        // segment (16-lane) reduce of the p-quad across n=ng
        float q0=e0, q1=e1, q2=e2, q3=e3;
        #pragma unroll
        for (int o = 1; o <= 8; o <<= 1) {
            q0 += __shfl_xor_sync(~0u, q0, o);
            q1 += __shfl_xor_sync(~0u, q1, o);
            q2 += __shfl_xor_sync(~0u, q2, o);
            q3 += __shfl_xor_sync(~0u, q3, o);
        }
        float z = q0 + q1 + q2 + q3;          // full row sum over 64 np
        float izr = 1.f / z;
        *(float4*)&out_cmb[tok*NP + ng*4] = make_float4(e0*izr, e1*izr, e2*izr, e3*izr);
        *(float4*)&g_wnum[tok*NP + ng*4]  = make_float4(e0*inv, e1*inv, e2*inv, e3*inv);
        if (ng == 0) {
            *(float4*)&g_epart[tok*P] = make_float4(q0, q1, q2, q3);
            ptnl[0] += q0; ptnl[1] += q1; ptnl[2] += q2; ptnl[3] += q3;
        }
        znp[0] += e0; znp[1] += e1; znp[2] += e2; znp[3] += e3;
    }
    #pragma unroll
    for (int j = 0; j < 4; j++) zsm[(ng*4+j)*16 + tg] = znp[j];
    if (ng == 0) {
        #pragma unroll
        for (int j = 0; j < 4; j++) atomicAdd(&ptn_sm[j], ptnl[j]);
    }
    __syncthreads();
    if (t < 64) {
        float s = 0.f;
        #pragma unroll
        for (int k = 0; k < 16; k++) s += zsm[t*16 + k];
        atomicAdd(&g_Zd[b*NP + t], (double)s);
    }
    if (t < 4) atomicAdd(&g_ptn[b*P + t], (double)ptn_sm[t]);
}

// ---------------- finish Z stats ---------------------------------------------
__global__ void k_zb() {
    int t = threadIdx.x, w = t >> 5, lane = t & 31;
    if (w < B) {
        double z = g_Zd[w*NP + lane] + g_Zd[w*NP + lane + 32];
        #pragma unroll
        for (int o = 16; o > 0; o >>= 1) z += __shfl_xor_sync(~0u, z, o);
        if (lane == 0) { g_Zb[w] = z; g_iZb[w] = 1.0 / z; }
    }
    for (int i = t; i < B*NP; i += 256) g_Zf[i] = (float)(1.0 / g_Zd[i]);
}

// ---------------- xs GEMM (f32x2): xs[np][d] += sum_s w[s][np] x[s][d] -------
// tile: 64 np x 128 d; thread (ng 0..15: np quad, dg 0..15: 8 d)
__global__ void k_xs(const float* __restrict__ x) {
    __shared__ __align__(16) float2 w2[32*64];    // dup  16KB
    __shared__ __align__(16) float x_sm[32*128];  // 16KB
    __shared__ float rz[64];
    int t = threadIdx.x;
    int b = blockIdx.z, d0 = blockIdx.y * 128, s0 = blockIdx.x * 512;
    if (t < 64) rz[t] = g_Zf[b*NP + t];
    int ng = t >> 4, dg = t & 15;
    float2 acc[4][4];
    #pragma unroll
    for (int a = 0; a < 4; a++)
        #pragma unroll
        for (int j = 0; j < 4; j++) acc[a][j] = dup2(0.f);
    __syncthreads();
    for (int st = 0; st < 512; st += 32) {
        int sbase = b*S + s0 + st;
        {
            int lss = t >> 3, lnp = (t & 7) * 8;
            const float4* wr = (const float4*)(g_wnum + (size_t)(sbase+lss)*NP + lnp);
            float4 v0 = wr[0], v1 = wr[1];
            v0.x *= rz[lnp+0]; v0.y *= rz[lnp+1]; v0.z *= rz[lnp+2]; v0.w *= rz[lnp+3];
            v1.x *= rz[lnp+4]; v1.y *= rz[lnp+5]; v1.z *= rz[lnp+6]; v1.w *= rz[lnp+7];
            int wb = lss*64 + lnp;
            w2[wb+0]=dup2(v0.x); w2[wb+1]=dup2(v0.y); w2[wb+2]=dup2(v0.z); w2[wb+3]=dup2(v0.w);
            w2[wb+4]=dup2(v1.x); w2[wb+5]=dup2(v1.y); w2[wb+6]=dup2(v1.z); w2[wb+7]=dup2(v1.w);
        }
        {
            int lss = t >> 3, lx = (t & 7) * 16;
            const float4* xr = (const float4*)(x + (size_t)(sbase+lss)*D + d0 + lx);
            #pragma unroll
            for (int k = 0; k < 4; k++)
                *(float4*)&x_sm[lss*128 + lx + k*4] = xr[k];
        }
        __syncthreads();
        #pragma unroll 2
        for (int ss = 0; ss < 32; ss++) {
            float4 xv0 = *(const float4*)&x_sm[ss*128 + dg*8];
            float4 xv1 = *(const float4*)&x_sm[ss*128 + dg*8 + 4];
            float2 xp[4] = { make_float2(xv0.x,xv0.y), make_float2(xv0.z,xv0.w),
                             make_float2(xv1.x,xv1.y), make_float2(xv1.z,xv1.w) };
            #pragma unroll
            for (int a = 0; a < 4; a++) {
                float2 w = w2[ss*64 + ng*4 + a];
                #pragma unroll
                for (int j = 0; j < 4; j++) acc[a][j] = ffma2(w, xp[j], acc[a][j]);
            }
        }
        __syncthreads();
    }
    #pragma unroll
    for (int a = 0; a < 4; a++) {
        float* dst = &g_xs[(size_t)(b*NP + ng*4 + a)*D + d0 + dg*8];
        #pragma unroll
        for (int j = 0; j < 4; j++) {
            atomicAdd(dst + j*2,     acc[a][j].x);
            atomicAdd(dst + j*2 + 1, acc[a][j].y);
        }
    }
}

// ---------------- FFN1: h = silu(xs@W1 + b1) ---------------------------------
// tile: 32 tok x 256 h; thread (tg 0..7: 4 tok, hg 0..31: 8 h)
__global__ void k_ffn1(const float* __restrict__ W1, const float* __restrict__ b1) {
    __shared__ __align__(16) float2 a2[32*32];    // dup 8KB
    __shared__ __align__(16) float  w_sm[32*256]; // 32KB
    int t = threadIdx.x;
    int n = blockIdx.x, h0 = blockIdx.y * 256;
    int tg = t >> 5, hg = t & 31;
    float2 acc[4][4];
    #pragma unroll
    for (int i = 0; i < 4; i++)
        #pragma unroll
        for (int j = 0; j < 4; j++) acc[i][j] = dup2(0.f);
    const float* Wb = W1 + (size_t)n*D*H + h0;
    for (int d0 = 0; d0 < D; d0 += 32) {
        {
            int lt = t >> 3, la = (t & 7) * 4;
            int bb = lt >> 2, pp = lt & 3;
            float4 v = *(const float4*)(g_xs + (size_t)(bb*NP + n*4 + pp)*D + d0 + la);
            int ab = lt*32 + la;
            a2[ab+0]=dup2(v.x); a2[ab+1]=dup2(v.y); a2[ab+2]=dup2(v.z); a2[ab+3]=dup2(v.w);
        }
        {
            int lwd = t >> 3, lwh = (t & 7) * 32;
            const float4* wr = (const float4*)(Wb + (size_t)(d0+lwd)*H + lwh);
            #pragma unroll
            for (int k = 0; k < 8; k++)
                *(float4*)&w_sm[lwd*256 + lwh + k*4] = wr[k];
        }
        __syncthreads();
        #pragma unroll 2
        for (int dd = 0; dd < 32; dd++) {
            float4 w01 = *(const float4*)&w_sm[dd*256 + hg*8];
            float4 w23 = *(const float4*)&w_sm[dd*256 + hg*8 + 4];
            float2 wp[4] = { make_float2(w01.x,w01.y), make_float2(w01.z,w01.w),
                             make_float2(w23.x,w23.y), make_float2(w23.z,w23.w) };
            #pragma unroll
            for (int i = 0; i < 4; i++) {
                float2 a = a2[(tg*4+i)*32 + dd];
                #pragma unroll
                for (int j = 0; j < 4; j++) acc[i][j] = ffma2(a, wp[j], acc[i][j]);
            }
        }
        __syncthreads();
    }
    float4 bv0 = *(const float4*)(b1 + n*H + h0 + hg*8);
    float4 bv1 = *(const float4*)(b1 + n*H + h0 + hg*8 + 4);
    #pragma unroll
    for (int i = 0; i < 4; i++) {
        int tk = tg*4 + i;
        float o[8] = { acc[i][0].x+bv0.x, acc[i][0].y+bv0.y, acc[i][1].x+bv0.z, acc[i][1].y+bv0.w,
                       acc[i][2].x+bv1.x, acc[i][2].y+bv1.y, acc[i][3].x+bv1.z, acc[i][3].y+bv1.w };
        #pragma unroll
        for (int k = 0; k < 8; k++) o[k] = o[k] / (1.f + expf(-o[k]));
        float* dst = &g_h[((size_t)n*ETOK + tk)*H + h0 + hg*8];
        *(float4*)dst       = make_float4(o[0], o[1], o[2], o[3]);
        *(float4*)(dst + 4) = make_float4(o[4], o[5], o[6], o[7]);
    }
}

// ---------------- FFN2: r = xs + h@W2 + b2 -----------------------------------
// tile: 32 tok x 128 d; thread (tg 0..7: 4 tok, dg 0..31: 4 d)
__global__ void k_ffn2(const float* __restrict__ W2, const float* __restrict__ b2) {
    __shared__ __align__(16) float2 a2[32*32];    // dup 8KB
    __shared__ __align__(16) float  w_sm[32*128]; // 16KB
    int t = threadIdx.x;
    int n = blockIdx.x, d0 = blockIdx.y * 128;
    int tg = t >> 5, dg = t & 31;
    float2 acc[4][2];
    #pragma unroll
    for (int i = 0; i < 4; i++) { acc[i][0] = dup2(0.f); acc[i][1] = dup2(0.f); }
    const float* Wb = W2 + (size_t)n*H*D + d0;
    for (int h0 = 0; h0 < H; h0 += 32) {
        {
            int lt = t >> 3, la = (t & 7) * 4;
            float4 v = *(const float4*)(g_h + ((size_t)n*ETOK + lt)*H + h0 + la);
            int ab = lt*32 + la;
            a2[ab+0]=dup2(v.x); a2[ab+1]=dup2(v.y); a2[ab+2]=dup2(v.z); a2[ab+3]=dup2(v.w);
        }
        {
            int lwh = t >> 3, lwd = (t & 7) * 16;
            const float4* wr = (const float4*)(Wb + (size_t)(h0+lwh)*D + lwd);
            #pragma unroll
            for (int k = 0; k < 4; k++)
                *(float4*)&w_sm[lwh*128 + lwd + k*4] = wr[k];
        }
        __syncthreads();
        #pragma unroll 4
        for (int hh = 0; hh < 32; hh++) {
            float4 wv = *(const float4*)&w_sm[hh*128 + dg*4];
            float2 w0 = make_float2(wv.x, wv.y), w1 = make_float2(wv.z, wv.w);
            #pragma unroll
            for (int i = 0; i < 4; i++) {
                float2 a = a2[(tg*4+i)*32 + hh];
                acc[i][0] = ffma2(a, w0, acc[i][0]);
                acc[i][1] = ffma2(a, w1, acc[i][1]);
            }
        }
        __syncthreads();
    }
    float4 b2v = *(const float4*)(b2 + n*D + d0 + dg*4);
    #pragma unroll
    for (int i = 0; i < 4; i++) {
        int tk = tg*4 + i;
        int bb = tk >> 2, pp = tk & 3;
        float4 xsv = *(const float4*)(g_xs + (size_t)(bb*NP + n*4 + pp)*D + d0 + dg*4);
        float4 r = make_float4(xsv.x + acc[i][0].x + b2v.x,
                               xsv.y + acc[i][0].y + b2v.y,
                               xsv.z + acc[i][1].x + b2v.z,
                               xsv.w + acc[i][1].y + b2v.w);
        *(float4*)&g_r[((size_t)n*ETOK + tk)*D + d0 + dg*4] = r;
    }
}

// ---------------- LayerNorm per expert-token row ----------------------------
__global__ void k_ln(const float* __restrict__ ln_g, const float* __restrict__ ln_b) {
    int row = blockIdx.x;
    int n = row >> 5, tk = row & 31;
    int t = threadIdx.x;
    const float* r = g_r + (size_t)row*D;
    float v[4]; float s = 0.f, s2 = 0.f;
    #pragma unroll
    for (int k = 0; k < 4; k++) { v[k] = r[t + k*256]; s += v[k]; s2 += v[k]*v[k]; }
    __shared__ float rs[256], rs2[256];
    rs[t] = s; rs2[t] = s2; __syncthreads();
    for (int o = 128; o > 0; o >>= 1) {
        if (t < o) { rs[t] += rs[t+o]; rs2[t] += rs2[t+o]; }
        __syncthreads();
    }
    float mu = rs[0] / D;
    float var = rs2[0] / D - mu*mu;
    float rstd = rsqrtf(var + LN_EPS);
    int bb = tk >> 2, pp = tk & 3;
    float* o = g_ys + (size_t)(bb*NP + n*4 + pp)*D;
    #pragma unroll
    for (int k = 0; k < 4; k++) {
        int d = t + k*256;
        o[d] = (v[k] - mu) * rstd * ln_g[n*D + d] + ln_b[n*D + d];
    }
}

// ---------------- combine: out[p][b][s][d] = sum_n ys cmb --------------------
// block: 256 thr = (p 0..3) x (dx 0..63 -> 4 d each); ys in regs, cmb dup in smem
__global__ void k_combine(const float* __restrict__ cmb, float* __restrict__ out) {
    __shared__ __align__(16) float2 cmb_dup[4*64*16];   // [p][s][n] dup, 32KB
    int t = threadIdx.x;
    int b = blockIdx.z, d0 = blockIdx.y * 256, s0 = blockIdx.x * 512;
    int p = t >> 6, dx = t & 63;
    float2 ysr[16][2];
    #pragma unroll
    for (int n = 0; n < 16; n++) {
        float4 v = *(const float4*)(g_ys + (size_t)(b*NP + n*4 + p)*D + d0 + dx*4);
        ysr[n][0] = make_float2(v.x, v.y);
        ysr[n][1] = make_float2(v.z, v.w);
    }
    int ls = t >> 2, lj = t & 3;
    for (int ph = 0; ph < 8; ph++) {
        int sbase = s0 + ph*64;
        __syncthreads();
        const float4* cr = (const float4*)(cmb + (size_t)(b*S + sbase + ls)*NP + lj*16);
        #pragma unroll
        for (int k = 0; k < 4; k++) {
            float4 c = cr[k];
            int nn = lj*4 + k;
            cmb_dup[(0*64 + ls)*16 + nn] = dup2(c.x);
            cmb_dup[(1*64 + ls)*16 + nn] = dup2(c.y);
            cmb_dup[(2*64 + ls)*16 + nn] = dup2(c.z);
            cmb_dup[(3*64 + ls)*16 + nn] = dup2(c.w);
        }
        __syncthreads();
        for (int s = 0; s < 64; s++) {
            const float2* cd = &cmb_dup[(p*64 + s)*16];
            float2 a0 = dup2(0.f), a1 = dup2(0.f);
            #pragma unroll
            for (int n = 0; n < 16; n++) {
                float2 c = cd[n];
                a0 = ffma2(c, ysr[n][0], a0);
                a1 = ffma2(c, ysr[n][1], a1);
            }
            float* dst = out + ((size_t)p*B + b)*S*D + (size_t)(sbase + s)*D + d0 + dx*4;
            *(float4*)dst = make_float4(a0.x, a0.y, a1.x, a1.y);
        }
    }
}

// ---------------- mutual info loss -------------------------------------------
__global__ void k_mi() {
    __shared__ double red[256];
    int t = threadIdx.x;
    int tok = blockIdx.x * 256 + t;
    int b = tok >> 12;
    double iZb = g_iZb[b];
    double pv[P]; double pm = 0.0;
    #pragma unroll
    for (int p = 0; p < P; p++) { pv[p] = (double)g_epart[tok*P + p] * iZb; pm += pv[p]; }
    double term = 0.0;
    #pragma unroll
    for (int p = 0; p < P; p++) {
        double pt_p = g_ptn[b*P + p] * iZb;
        double ratio = pv[p] / (pm * pt_p) + 1e-10;
        term += pv[p] * log(ratio);
    }
    red[t] = term; __syncthreads();
    for (int o = 128; o > 0; o >>= 1) { if (t < o) red[t] += red[t+o]; __syncthreads(); }
    if (t == 0) atomicAdd(&g_mi, red[0]);
}

__global__ void k_fin(float* __restrict__ out_mi) {
    out_mi[0] = (float)(-g_mi);
}

// ---------------- launch -----------------------------------------------------
extern "C" void kernel_launch(void* const* d_in, const int* in_sizes, int n_in,
                              void* d_out, int out_size) {
    const float* x        = (const float*)d_in[0];
    const float* phi      = (const float*)d_in[1];
    const float* scale    = (const float*)d_in[2];
    const float* task_emb = (const float*)d_in[3];
    const float* W1       = (const float*)d_in[4];
    const float* b1       = (const float*)d_in[5];
    const float* W2       = (const float*)d_in[6];
    const float* b2       = (const float*)d_in[7];
    const float* ln_g     = (const float*)d_in[8];
    const float* ln_b     = (const float*)d_in[9];
    float* out = (float*)d_out;
    float* out_cmb = out + (size_t)P*B*S*D;
    float* out_mi  = out_cmb + (size_t)B*S*NP;

    k_init<<<2048, 256>>>(task_emb);
    k_ph<<<NP, 256>>>(phi, scale);
    k_logits<<<TOK/64, 256>>>(x, out_cmb);
    k_zb<<<1, 256>>>();
    k_xs<<<dim3(8, 8, B), 256>>>(x);
    k_ffn1<<<dim3(NEXP, H/256), 256>>>(W1, b1);
    k_ffn2<<<dim3(NEXP, D/128), 256>>>(W2, b2);
    k_ln<<<NEXP*ETOK, 256>>>(ln_g, ln_b);
    k_combine<<<dim3(8, 4, B), 256>>>(out_cmb, out);
    k_mi<<<TOK/256, 256>>>();
    k_fin<<<1, 1>>>(out_mi);
}